// round 6
// baseline (speedup 1.0000x reference)
#include <cuda_runtime.h>
#include <cuda_bf16.h>
#include <cstdint>

// Z[b,w,t] = sum_c Q[b,w,c] * ( K[b,w+t,c] + bias[c,t] ),  B=16, T=1024, C=128.
//
// Per 128x128 output tile (b, w0, t0), u0 = w0 + t0. Six 128x64 half-GEMMs:
//   PB_h[i,s] = Q . bias[:, t0+64h+s]          -> Z[i, 64h+s]          (STG)
//   Pj  [i,s] = Q . K[u0+64j+s, :], j=0..3     -> Z[i, 64j+s-i] if in [0,128)  (RMW)
// Each GEMM: merged k-loop AhBh + AhBl + AlBh (bf16 hi/lo split, fp32 accum).
// smem 96KB, 256 threads -> 2 CTAs/SM so staging/epilogue of one CTA overlaps
// the other CTA's tensor-core GEMMs. Z lives in global (L2-hot RMW).

#define TDIM   1024
#define CDIM   128
#define KROWS  2047
#define NTHREADS 256

// smem (bytes): Q 128 rows x 256B hi/lo; B 64 rows x 256B hi/lo. XOR-swizzled.
#define OQH 0
#define OQL 32768
#define OBH 65536
#define OBL 81920
#define SMEM_BYTES 98304

__device__ __forceinline__ void ldsm4(uint32_t addr, uint32_t& r0, uint32_t& r1,
                                      uint32_t& r2, uint32_t& r3) {
    asm volatile("ldmatrix.sync.aligned.m8n8.x4.shared.b16 {%0,%1,%2,%3}, [%4];"
                 : "=r"(r0), "=r"(r1), "=r"(r2), "=r"(r3) : "r"(addr));
}
__device__ __forceinline__ void mma16816(float* d, uint32_t a0, uint32_t a1,
                                         uint32_t a2, uint32_t a3,
                                         uint32_t b0, uint32_t b1) {
    asm volatile("mma.sync.aligned.m16n8k16.row.col.f32.bf16.bf16.f32 "
                 "{%0,%1,%2,%3}, {%4,%5,%6,%7}, {%8,%9}, {%0,%1,%2,%3};"
                 : "+f"(d[0]), "+f"(d[1]), "+f"(d[2]), "+f"(d[3])
                 : "r"(a0), "r"(a1), "r"(a2), "r"(a3), "r"(b0), "r"(b1));
}
__device__ __forceinline__ uint32_t smem_u32(const void* p) {
    uint32_t a;
    asm("{ .reg .u64 t; cvta.to.shared.u64 t, %1; cvt.u32.u64 %0, t; }" : "=r"(a) : "l"(p));
    return a;
}

__device__ __forceinline__ uint32_t pack_hi_lo(float x, float y, uint32_t& lo_out) {
    __nv_bfloat16 hx = __float2bfloat16(x);
    __nv_bfloat16 hy = __float2bfloat16(y);
    __nv_bfloat16 lx = __float2bfloat16(x - __bfloat162float(hx));
    __nv_bfloat16 ly = __float2bfloat16(y - __bfloat162float(hy));
    __nv_bfloat162 h = __nv_bfloat162(hx, hy);
    __nv_bfloat162 l = __nv_bfloat162(lx, ly);
    lo_out = *reinterpret_cast<uint32_t*>(&l);
    return *reinterpret_cast<uint32_t*>(&h);
}

// store float4 (4 c-values) of row `row` at c = cv*4 into hi/lo bf16 buffers
__device__ __forceinline__ void st_hilo4(char* sm, int bufH, int bufL,
                                         int row, int cv, float4 v) {
    uint32_t l01, l23;
    uint32_t h01 = pack_hi_lo(v.x, v.y, l01);
    uint32_t h23 = pack_hi_lo(v.z, v.w, l23);
    int c2 = cv >> 1;                       // 16B chunk index 0..15
    uint32_t off = (uint32_t)(row * 256 + (((c2) ^ (row & 7)) << 4) + (cv & 1) * 8);
    *reinterpret_cast<uint2*>(sm + bufH + off) = make_uint2(h01, h23);
    *reinterpret_cast<uint2*>(sm + bufL + off) = make_uint2(l01, l23);
}

__global__ __launch_bounds__(NTHREADS, 2)
void sw_hmma_kernel(const float* __restrict__ Q,
                    const float* __restrict__ Km,
                    const float* __restrict__ bias,
                    float* __restrict__ Z)
{
    extern __shared__ char smem[];
    const uint32_t sb = smem_u32(smem);

    const int tid  = threadIdx.x;
    const int wid  = tid >> 5;
    const int lane = tid & 31;
    const int wr   = wid >> 1;          // warp row 0..3  -> rows [wr*32, +32)
    const int wc   = wid & 1;           // warp col 0..1  -> cols [wc*32, +32) of 64

    const int b  = blockIdx.z;
    const int w0 = blockIdx.y * 128;
    const int t0 = blockIdx.x * 128;
    const int u0 = w0 + t0;

    const float* Qb = Q  + ((size_t)b * TDIM) * CDIM;
    const float* Kb = Km + ((size_t)b * KROWS) * CDIM;
    float* Zb = Z + ((size_t)b * TDIM + w0) * TDIM + t0;

    // ---- lane-invariant ldmatrix address components ----
    const uint32_t rx   = lane & 7;
    const uint32_t aC2  = lane >> 4;            // 0/1
    const uint32_t bC2  = (lane >> 3) & 1;      // 0/1
    uint32_t aRow[2], bRow[2];
#pragma unroll
    for (int mt = 0; mt < 2; mt++)
        aRow[mt] = (uint32_t)((wr * 32 + mt * 16 + (lane & 15)) * 256);
#pragma unroll
    for (int p = 0; p < 2; p++)
        bRow[p] = (uint32_t)((wc * 32 + p * 16 + ((lane >> 4) << 3) + (lane & 7)) * 256);

    // epilogue fragment coords
    const int er = lane >> 2;
    const int ec = (lane & 3) * 2;

    float acc[2][2][4];

#define ZERO_ACC() do {                                                      \
    _Pragma("unroll") for (int _m = 0; _m < 2; _m++)                         \
    _Pragma("unroll") for (int _n = 0; _n < 2; _n++)                         \
    _Pragma("unroll") for (int _e = 0; _e < 4; _e++) acc[_m][_n][_e] = 0.f;  \
} while (0)

    // merged 3-pass half-GEMM (128x64): per kstep 8 LDSM + 12 MMA
#define GEMM_MERGED() do {                                                   \
    ZERO_ACC();                                                              \
    _Pragma("unroll")                                                        \
    for (int st = 0; st < 8; st++) {                                         \
        uint32_t kc = 2u * (uint32_t)st;                                     \
        uint32_t aoff = ((kc + aC2) ^ rx) << 4;                              \
        uint32_t boff = ((kc + bC2) ^ rx) << 4;                              \
        uint32_t ah0,ah1,ah2,ah3,ah4,ah5,ah6,ah7;                            \
        uint32_t al0,al1,al2,al3,al4,al5,al6,al7;                            \
        uint32_t bh0,bh1,bh2,bh3,bh4,bh5,bh6,bh7;                            \
        uint32_t bl0,bl1,bl2,bl3,bl4,bl5,bl6,bl7;                            \
        ldsm4(sb + OQH + aRow[0] + aoff, ah0,ah1,ah2,ah3);                   \
        ldsm4(sb + OQH + aRow[1] + aoff, ah4,ah5,ah6,ah7);                   \
        ldsm4(sb + OQL + aRow[0] + aoff, al0,al1,al2,al3);                   \
        ldsm4(sb + OQL + aRow[1] + aoff, al4,al5,al6,al7);                   \
        ldsm4(sb + OBH + bRow[0] + boff, bh0,bh1,bh2,bh3);                   \
        ldsm4(sb + OBH + bRow[1] + boff, bh4,bh5,bh6,bh7);                   \
        ldsm4(sb + OBL + bRow[0] + boff, bl0,bl1,bl2,bl3);                   \
        ldsm4(sb + OBL + bRow[1] + boff, bl4,bl5,bl6,bl7);                   \
        /* Ah * Bh */                                                        \
        mma16816(acc[0][0], ah0,ah1,ah2,ah3, bh0,bh1);                       \
        mma16816(acc[0][0], ah0,ah1,ah2,ah3, bl0,bl1);                       \
        mma16816(acc[0][0], al0,al1,al2,al3, bh0,bh1);                       \
        mma16816(acc[0][1], ah0,ah1,ah2,ah3, bh2,bh3);                       \
        mma16816(acc[0][1], ah0,ah1,ah2,ah3, bl2,bl3);                       \
        mma16816(acc[0][1], al0,al1,al2,al3, bh2,bh3);                       \
        mma16816(acc[1][0], ah4,ah5,ah6,ah7, bh0,bh1);                       \
        mma16816(acc[1][0], ah4,ah5,ah6,ah7, bl0,bl1);                       \
        mma16816(acc[1][0], al4,al5,al6,al7, bh0,bh1);                       \
        mma16816(acc[1][1], ah4,ah5,ah6,ah7, bh2,bh3);                       \
        mma16816(acc[1][1], ah4,ah5,ah6,ah7, bl2,bl3);                       \
        mma16816(acc[1][1], al4,al5,al6,al7, bh2,bh3);                       \
        /* note bh4..7/bl4..7 pair with nt=1 frags */                        \
        mma16816(acc[0][1], ah0,ah1,ah2,ah3, bh4,bh5);                       \
        (void)bh6; (void)bh7; (void)bl6; (void)bl7; (void)bl4; (void)bl5;    \
    }                                                                        \
} while (0)

    // The macro above is WRONG for nt mapping; use explicit version below.
#undef GEMM_MERGED
#define GEMM_MERGED() do {                                                   \
    ZERO_ACC();                                                              \
    _Pragma("unroll")                                                        \
    for (int st = 0; st < 8; st++) {                                         \
        uint32_t kc = 2u * (uint32_t)st;                                     \
        uint32_t aoff = ((kc + aC2) ^ rx) << 4;                              \
        uint32_t boff = ((kc + bC2) ^ rx) << 4;                              \
        uint32_t ah0,ah1,ah2,ah3,ah4,ah5,ah6,ah7;                            \
        uint32_t al0,al1,al2,al3,al4,al5,al6,al7;                            \
        uint32_t bh0,bh1,bh2,bh3,bh4,bh5,bh6,bh7;                            \
        uint32_t bl0,bl1,bl2,bl3,bl4,bl5,bl6,bl7;                            \
        ldsm4(sb + OQH + aRow[0] + aoff, ah0,ah1,ah2,ah3);                   \
        ldsm4(sb + OQH + aRow[1] + aoff, ah4,ah5,ah6,ah7);                   \
        ldsm4(sb + OQL + aRow[0] + aoff, al0,al1,al2,al3);                   \
        ldsm4(sb + OQL + aRow[1] + aoff, al4,al5,al6,al7);                   \
        ldsm4(sb + OBH + bRow[0] + boff, bh0,bh1,bh2,bh3);                   \
        ldsm4(sb + OBH + bRow[1] + boff, bh4,bh5,bh6,bh7);                   \
        ldsm4(sb + OBL + bRow[0] + boff, bl0,bl1,bl2,bl3);                   \
        ldsm4(sb + OBL + bRow[1] + boff, bl4,bl5,bl6,bl7);                   \
        /* bRow[0] frags (bh0..3) cover n = wc*32 + {0..7, 8..15};           \
           bRow[1] frags (bh4..7) cover n = wc*32 + {16..23, 24..31}. */     \
        mma16816(acc[0][0], ah0,ah1,ah2,ah3, bh0,bh1);                       \
        mma16816(acc[0][1], ah0,ah1,ah2,ah3, bh2,bh3);                       \
        mma16816(acc[0][2], ah0,ah1,ah2,ah3, bh4,bh5);                       \
        mma16816(acc[0][3], ah0,ah1,ah2,ah3, bh6,bh7);                       \
        mma16816(acc[1][0], ah4,ah5,ah6,ah7, bh0,bh1);                       \
        mma16816(acc[1][1], ah4,ah5,ah6,ah7, bh2,bh3);                       \
        mma16816(acc[1][2], ah4,ah5,ah6,ah7, bh4,bh5);                       \
        mma16816(acc[1][3], ah4,ah5,ah6,ah7, bh6,bh7);                       \
        mma16816(acc[0][0], ah0,ah1,ah2,ah3, bl0,bl1);                       \
        mma16816(acc[0][1], ah0,ah1,ah2,ah3, bl2,bl3);                       \
        mma16816(acc[0][2], ah0,ah1,ah2,ah3, bl4,bl5);                       \
        mma16816(acc[0][3], ah0,ah1,ah2,ah3, bl6,bl7);                       \
        mma16816(acc[1][0], ah4,ah5,ah6,ah7, bl0,bl1);                       \
        mma16816(acc[1][1], ah4,ah5,ah6,ah7, bl2,bl3);                       \
        mma16816(acc[1][2], ah4,ah5,ah6,ah7, bl4,bl5);                       \
        mma16816(acc[1][3], ah4,ah5,ah6,ah7, bl6,bl7);                       \
        mma16816(acc[0][0], al0,al1,al2,al3, bh0,bh1);                       \
        mma16816(acc[0][1], al0,al1,al2,al3, bh2,bh3);                       \
        mma16816(acc[0][2], al0,al1,al2,al3, bh4,bh5);                       \
        mma16816(acc[0][3], al0,al1,al2,al3, bh6,bh7);                       \
        mma16816(acc[1][0], al4,al5,al6,al7, bh0,bh1);                       \
        mma16816(acc[1][1], al4,al5,al6,al7, bh2,bh3);                       \
        mma16816(acc[1][2], al4,al5,al6,al7, bh4,bh5);                       \
        mma16816(acc[1][3], al4,al5,al6,al7, bh6,bh7);                       \
    }                                                                        \
} while (0)

    // redefine acc with nt dimension 4 (n = wc*32 + nt*8)
    float accv[2][4][4];
#undef ZERO_ACC
#define ZERO_ACC() do {                                                      \
    _Pragma("unroll") for (int _m = 0; _m < 2; _m++)                         \
    _Pragma("unroll") for (int _n = 0; _n < 4; _n++)                         \
    _Pragma("unroll") for (int _e = 0; _e < 4; _e++) accv[_m][_n][_e] = 0.f; \
} while (0)
#define acc accv

    // ---- staging helpers (inline loops) ----
#define STAGE_Q() do {                                                       \
    _Pragma("unroll")                                                        \
    for (int r = 0; r < 16; r++) {                                           \
        int idx = tid + NTHREADS * r;                                        \
        int row = idx >> 5, cv = idx & 31;                                   \
        float4 v = *reinterpret_cast<const float4*>(                         \
            Qb + (size_t)(w0 + row) * CDIM + cv * 4);                        \
        st_hilo4(smem, OQH, OQL, row, cv, v);                                \
    }                                                                        \
} while (0)

#define STAGE_K_HALF(J) do {                                                 \
    _Pragma("unroll")                                                        \
    for (int r = 0; r < 8; r++) {                                            \
        int idx = tid + NTHREADS * r;                                        \
        int row = idx >> 5, cv = idx & 31;                                   \
        int u = u0 + 64 * (J) + row;                                         \
        if (u > 2046) u = 2046;                                              \
        float4 v = *reinterpret_cast<const float4*>(                         \
            Kb + (size_t)u * CDIM + cv * 4);                                 \
        st_hilo4(smem, OBH, OBL, row, cv, v);                                \
    }                                                                        \
} while (0)

    // bias half H: rows tau in [0,64), data over c (strided gather, R4-style)
#define STAGE_BIAS_HALF(H) do {                                              \
    const int tau = tid >> 2;                                                \
    const int cb  = (tid & 3) * 32;                                          \
    float f[32];                                                             \
    _Pragma("unroll")                                                        \
    for (int j = 0; j < 32; j++)                                             \
        f[j] = __ldg(bias + (size_t)(cb + j) * TDIM + t0 + 64 * (H) + tau);  \
    _Pragma("unroll")                                                        \
    for (int j = 0; j < 16; j++) {                                           \
        uint32_t lo;                                                         \
        uint32_t hi = pack_hi_lo(f[2 * j], f[2 * j + 1], lo);                \
        int c = cb + 2 * j;                                                  \
        int c2 = c >> 3;                                                     \
        uint32_t off = (uint32_t)(tau * 256 + ((c2 ^ (tau & 7)) << 4)        \
                                  + ((c * 2) & 15));                         \
        *reinterpret_cast<uint32_t*>(smem + OBH + off) = hi;                 \
        *reinterpret_cast<uint32_t*>(smem + OBL + off) = lo;                 \
    }                                                                        \
} while (0)

    // PB epilogue: plain STG float2 to Z[:, 64h + s]
#define STORE_PB(H) do {                                                     \
    _Pragma("unroll") for (int mt = 0; mt < 2; mt++)                         \
    _Pragma("unroll") for (int nt = 0; nt < 4; nt++)                         \
    _Pragma("unroll") for (int ep = 0; ep < 2; ep++) {                       \
        int i = wr * 32 + mt * 16 + er + 8 * ep;                             \
        int tau = 64 * (H) + wc * 32 + nt * 8 + ec;                          \
        float2 v = make_float2(acc[mt][nt][2 * ep], acc[mt][nt][2 * ep + 1]);\
        *reinterpret_cast<float2*>(Zb + (size_t)i * TDIM + tau) = v;         \
    }                                                                        \
} while (0)

    // K epilogue: Z[i, 64j + s - i] += acc, predicated, scalar RMW
#define RMW_PK(J) do {                                                       \
    _Pragma("unroll") for (int mt = 0; mt < 2; mt++)                         \
    _Pragma("unroll") for (int nt = 0; nt < 4; nt++)                         \
    _Pragma("unroll") for (int e = 0; e < 4; e++) {                          \
        int i = wr * 32 + mt * 16 + er + ((e & 2) ? 8 : 0);                  \
        int s = wc * 32 + nt * 8 + ec + (e & 1);                             \
        int tau = 64 * (J) + s - i;                                          \
        if (tau >= 0 && tau < 128) {                                         \
            float* p = Zb + (size_t)i * TDIM + tau;                          \
            *p += acc[mt][nt][e];                                            \
        }                                                                    \
    }                                                                        \
} while (0)

    // ================= phase sequence =================
    STAGE_Q();
    STAGE_BIAS_HALF(0);
    __syncthreads();

    GEMM_MERGED();                    // PB half 0
    __syncthreads();
    STORE_PB(0);
    STAGE_BIAS_HALF(1);
    __syncthreads();

    GEMM_MERGED();                    // PB half 1
    __syncthreads();
    STORE_PB(1);
    STAGE_K_HALF(0);
    __syncthreads();

    GEMM_MERGED();                    // P, K rows u0+[0,64)
    __syncthreads();
    RMW_PK(0);
    STAGE_K_HALF(1);
    __syncthreads();

    GEMM_MERGED();                    // u0+[64,128)
    __syncthreads();
    RMW_PK(1);
    STAGE_K_HALF(2);
    __syncthreads();

    GEMM_MERGED();                    // u0+[128,192)
    __syncthreads();
    RMW_PK(2);
    STAGE_K_HALF(3);
    __syncthreads();

    GEMM_MERGED();                    // u0+[192,255]
    __syncthreads();
    RMW_PK(3);

#undef acc
#undef GEMM_MERGED
#undef ZERO_ACC
#undef STAGE_Q
#undef STAGE_K_HALF
#undef STAGE_BIAS_HALF
#undef STORE_PB
#undef RMW_PK
}

extern "C" void kernel_launch(void* const* d_in, const int* in_sizes, int n_in,
                              void* d_out, int out_size)
{
    const float* Q    = (const float*)d_in[0];   // (16, 1024, 128)
    const float* Km   = (const float*)d_in[1];   // (16, 2047, 128)
    const float* bias = (const float*)d_in[2];   // (1, 1, 128, 1024)
    float* Z          = (float*)d_out;           // (16, 1024, 1024)

    cudaFuncSetAttribute(sw_hmma_kernel, cudaFuncAttributeMaxDynamicSharedMemorySize, SMEM_BYTES);
    dim3 grid(TDIM / 128, TDIM / 128, 16);       // (8, 8, 16) = 1024 CTAs
    sw_hmma_kernel<<<grid, NTHREADS, SMEM_BYTES>>>(Q, Km, bias, Z);
}

// round 7
// speedup vs baseline: 1.8051x; 1.8051x over previous
#include <cuda_runtime.h>
#include <cuda_bf16.h>
#include <cstdint>

// Z[b,w,t] = sum_c Q[b,w,c] * ( K[b,w+t,c] + bias[c,t] ),  B=16, T=1024, C=128.
//
// Kernel 1 (pb): Z[b, w0+i, t0+s] = sum_c Q[w0+i,c] * bias[c, t0+s]   (STG)
// Kernel 2 (band): per warp m-tile im=16*mt, half h:
//   D[r,j] = sum_c Q[w0+im+r, c] * K[u0+im+j, c],  j in [80h, 80h+80)
//   Z[w0+im+r, j-r] += D[r,j]   for 0 <= j-r < 128   (RMW, L2-hot)
// Both GEMMs: merged k-loop AhBh + AhBl + AlBh (bf16 hi/lo split, fp32 accum).

#define TDIM   1024
#define CDIM   128
#define KROWS  2047
#define NTHREADS 512

// ---------------- common helpers ----------------
__device__ __forceinline__ void ldsm4(uint32_t addr, uint32_t& r0, uint32_t& r1,
                                      uint32_t& r2, uint32_t& r3) {
    asm volatile("ldmatrix.sync.aligned.m8n8.x4.shared.b16 {%0,%1,%2,%3}, [%4];"
                 : "=r"(r0), "=r"(r1), "=r"(r2), "=r"(r3) : "r"(addr));
}
__device__ __forceinline__ void mma16816(float* d, uint32_t a0, uint32_t a1,
                                         uint32_t a2, uint32_t a3,
                                         uint32_t b0, uint32_t b1) {
    asm volatile("mma.sync.aligned.m16n8k16.row.col.f32.bf16.bf16.f32 "
                 "{%0,%1,%2,%3}, {%4,%5,%6,%7}, {%8,%9}, {%0,%1,%2,%3};"
                 : "+f"(d[0]), "+f"(d[1]), "+f"(d[2]), "+f"(d[3])
                 : "r"(a0), "r"(a1), "r"(a2), "r"(a3), "r"(b0), "r"(b1));
}
__device__ __forceinline__ uint32_t smem_u32(const void* p) {
    uint32_t a;
    asm("{ .reg .u64 t; cvta.to.shared.u64 t, %1; cvt.u32.u64 %0, t; }" : "=r"(a) : "l"(p));
    return a;
}
__device__ __forceinline__ uint32_t pack_hi_lo(float x, float y, uint32_t& lo_out) {
    __nv_bfloat16 hx = __float2bfloat16(x);
    __nv_bfloat16 hy = __float2bfloat16(y);
    __nv_bfloat16 lx = __float2bfloat16(x - __bfloat162float(hx));
    __nv_bfloat16 ly = __float2bfloat16(y - __bfloat162float(hy));
    __nv_bfloat162 h = __nv_bfloat162(hx, hy);
    __nv_bfloat162 l = __nv_bfloat162(lx, ly);
    lo_out = *reinterpret_cast<uint32_t*>(&l);
    return *reinterpret_cast<uint32_t*>(&h);
}
// store float4 (4 c-values) of row `row` at c = cv*4 into hi/lo bf16 buffers
// (rows are 256B; 16B chunks XOR-swizzled by row&7)
__device__ __forceinline__ void st_hilo4(char* sm, int bufH, int bufL,
                                         int row, int cv, float4 v) {
    uint32_t l01, l23;
    uint32_t h01 = pack_hi_lo(v.x, v.y, l01);
    uint32_t h23 = pack_hi_lo(v.z, v.w, l23);
    int c2 = cv >> 1;
    uint32_t off = (uint32_t)(row * 256 + (((c2) ^ (row & 7)) << 4) + (cv & 1) * 8);
    *reinterpret_cast<uint2*>(sm + bufH + off) = make_uint2(h01, h23);
    *reinterpret_cast<uint2*>(sm + bufL + off) = make_uint2(l01, l23);
}

// =====================================================================
// Kernel 1: Z = Q @ bias  (per 128x128 tile, direct store)
// =====================================================================
#define P_OQH 0
#define P_OQL 32768
#define P_OBH 65536
#define P_OBL 98304
#define SMEM1  131072

__global__ __launch_bounds__(NTHREADS, 1)
void pb_kernel(const float* __restrict__ Q,
               const float* __restrict__ bias,
               float* __restrict__ Z)
{
    extern __shared__ char smem[];
    const uint32_t sb = smem_u32(smem);

    const int tid  = threadIdx.x;
    const int wid  = tid >> 5;
    const int lane = tid & 31;
    const int wr   = wid >> 2;          // 0..3
    const int wc   = wid & 3;           // 0..3

    const int b  = blockIdx.z;
    const int w0 = blockIdx.y * 128;
    const int t0 = blockIdx.x * 128;

    const float* Qb = Q + ((size_t)b * TDIM) * CDIM;
    float* Zb = Z + ((size_t)b * TDIM + w0) * TDIM + t0;

    const uint32_t rx  = lane & 7;
    const uint32_t aC2 = lane >> 4;
    const uint32_t bC2 = (lane >> 3) & 1;
    uint32_t aRow[2], bRow[2];
#pragma unroll
    for (int mt = 0; mt < 2; mt++)
        aRow[mt] = (uint32_t)((wr * 32 + mt * 16 + (lane & 15)) * 256);
#pragma unroll
    for (int p = 0; p < 2; p++)
        bRow[p] = (uint32_t)((wc * 32 + p * 16 + ((lane >> 4) << 3) + (lane & 7)) * 256);

    const int er = lane >> 2;
    const int ec = (lane & 3) * 2;

    // ---- stage Q (hi/lo) ----
#pragma unroll
    for (int r = 0; r < 8; r++) {
        int idx = tid + NTHREADS * r;           // 4096 float4
        int row = idx >> 5, cv = idx & 31;
        float4 v = *reinterpret_cast<const float4*>(Qb + (size_t)(w0 + row) * CDIM + cv * 4);
        st_hilo4(smem, P_OQH, P_OQL, row, cv, v);
    }
    // ---- stage bias: rows = tau, cols = c (strided gather, sector-efficient) ----
    {
        const int tau = tid >> 2;
        const int cb  = (tid & 3) * 32;
        float f[32];
#pragma unroll
        for (int j = 0; j < 32; j++)
            f[j] = __ldg(bias + (size_t)(cb + j) * TDIM + t0 + tau);
#pragma unroll
        for (int j = 0; j < 16; j++) {
            uint32_t lo;
            uint32_t hi = pack_hi_lo(f[2 * j], f[2 * j + 1], lo);
            int c = cb + 2 * j;
            int c2 = c >> 3;
            uint32_t off = (uint32_t)(tau * 256 + ((c2 ^ (tau & 7)) << 4) + ((c * 2) & 15));
            *reinterpret_cast<uint32_t*>(smem + P_OBH + off) = hi;
            *reinterpret_cast<uint32_t*>(smem + P_OBL + off) = lo;
        }
    }
    __syncthreads();

    // ---- merged 3-pass GEMM ----
    float acc[2][4][4];
#pragma unroll
    for (int m = 0; m < 2; m++)
#pragma unroll
        for (int n = 0; n < 4; n++)
#pragma unroll
            for (int e = 0; e < 4; e++) acc[m][n][e] = 0.f;

#pragma unroll
    for (int st = 0; st < 8; st++) {
        uint32_t kc = 2u * (uint32_t)st;
        uint32_t aoff = ((kc + aC2) ^ rx) << 4;
        uint32_t boff = ((kc + bC2) ^ rx) << 4;
        uint32_t ah0,ah1,ah2,ah3,ah4,ah5,ah6,ah7;
        uint32_t al0,al1,al2,al3,al4,al5,al6,al7;
        uint32_t bh0,bh1,bh2,bh3,bh4,bh5,bh6,bh7;
        uint32_t bl0,bl1,bl2,bl3,bl4,bl5,bl6,bl7;
        ldsm4(sb + P_OQH + aRow[0] + aoff, ah0,ah1,ah2,ah3);
        ldsm4(sb + P_OQH + aRow[1] + aoff, ah4,ah5,ah6,ah7);
        ldsm4(sb + P_OQL + aRow[0] + aoff, al0,al1,al2,al3);
        ldsm4(sb + P_OQL + aRow[1] + aoff, al4,al5,al6,al7);
        ldsm4(sb + P_OBH + bRow[0] + boff, bh0,bh1,bh2,bh3);
        ldsm4(sb + P_OBH + bRow[1] + boff, bh4,bh5,bh6,bh7);
        ldsm4(sb + P_OBL + bRow[0] + boff, bl0,bl1,bl2,bl3);
        ldsm4(sb + P_OBL + bRow[1] + boff, bl4,bl5,bl6,bl7);
        mma16816(acc[0][0], ah0,ah1,ah2,ah3, bh0,bh1);
        mma16816(acc[0][1], ah0,ah1,ah2,ah3, bh2,bh3);
        mma16816(acc[0][2], ah0,ah1,ah2,ah3, bh4,bh5);
        mma16816(acc[0][3], ah0,ah1,ah2,ah3, bh6,bh7);
        mma16816(acc[1][0], ah4,ah5,ah6,ah7, bh0,bh1);
        mma16816(acc[1][1], ah4,ah5,ah6,ah7, bh2,bh3);
        mma16816(acc[1][2], ah4,ah5,ah6,ah7, bh4,bh5);
        mma16816(acc[1][3], ah4,ah5,ah6,ah7, bh6,bh7);
        mma16816(acc[0][0], ah0,ah1,ah2,ah3, bl0,bl1);
        mma16816(acc[0][1], ah0,ah1,ah2,ah3, bl2,bl3);
        mma16816(acc[0][2], ah0,ah1,ah2,ah3, bl4,bl5);
        mma16816(acc[0][3], ah0,ah1,ah2,ah3, bl6,bl7);
        mma16816(acc[1][0], ah4,ah5,ah6,ah7, bl0,bl1);
        mma16816(acc[1][1], ah4,ah5,ah6,ah7, bl2,bl3);
        mma16816(acc[1][2], ah4,ah5,ah6,ah7, bl4,bl5);
        mma16816(acc[1][3], ah4,ah5,ah6,ah7, bl6,bl7);
        mma16816(acc[0][0], al0,al1,al2,al3, bh0,bh1);
        mma16816(acc[0][1], al0,al1,al2,al3, bh2,bh3);
        mma16816(acc[0][2], al0,al1,al2,al3, bh4,bh5);
        mma16816(acc[0][3], al0,al1,al2,al3, bh6,bh7);
        mma16816(acc[1][0], al4,al5,al6,al7, bh0,bh1);
        mma16816(acc[1][1], al4,al5,al6,al7, bh2,bh3);
        mma16816(acc[1][2], al4,al5,al6,al7, bh4,bh5);
        mma16816(acc[1][3], al4,al5,al6,al7, bh6,bh7);
    }

    // ---- epilogue: direct STG ----
#pragma unroll
    for (int mt = 0; mt < 2; mt++)
#pragma unroll
        for (int nt = 0; nt < 4; nt++) {
            int i0  = wr * 32 + mt * 16 + er;
            int tau = wc * 32 + nt * 8 + ec;
            *reinterpret_cast<float2*>(Zb + (size_t)i0 * TDIM + tau) =
                make_float2(acc[mt][nt][0], acc[mt][nt][1]);
            *reinterpret_cast<float2*>(Zb + (size_t)(i0 + 8) * TDIM + tau) =
                make_float2(acc[mt][nt][2], acc[mt][nt][3]);
        }
}

// =====================================================================
// Kernel 2: band GEMM, Z += Q @ K-band
// =====================================================================
#define B_OQH 0
#define B_OQL 32768
#define B_OPH 65536
#define PANEL_ROWS 272
#define PANEL_BYTES (PANEL_ROWS * 256)          // 69632
#define B_OPL (B_OPH + PANEL_BYTES)             // 135168
#define SMEM2 (B_OPL + PANEL_BYTES)             // 204800
#define ZSTRIDE 132                             // Z smem overlay at B_OPH

__global__ __launch_bounds__(NTHREADS, 1)
void band_kernel(const float* __restrict__ Q,
                 const float* __restrict__ Km,
                 float* __restrict__ Z)
{
    extern __shared__ char smem[];
    const uint32_t sb = smem_u32(smem);
    float* zs = reinterpret_cast<float*>(smem + B_OPH);

    const int tid  = threadIdx.x;
    const int wid  = tid >> 5;
    const int lane = tid & 31;
    const int mt   = wid >> 1;          // m-tile 0..7, rows [16mt, 16mt+16)
    const int h    = wid & 1;           // band half: j in [80h, 80h+80)
    const int im   = mt * 16;

    const int b  = blockIdx.z;
    const int w0 = blockIdx.y * 128;
    const int t0 = blockIdx.x * 128;
    const int u0 = w0 + t0;

    const float* Qb = Q  + ((size_t)b * TDIM) * CDIM;
    const float* Kb = Km + ((size_t)b * KROWS) * CDIM;
    float* Zb = Z + ((size_t)b * TDIM + w0) * TDIM + t0;

    const uint32_t rx  = lane & 7;
    const uint32_t aC2 = lane >> 4;
    const uint32_t bC2 = (lane >> 3) & 1;
    const uint32_t aRowB = (uint32_t)((im + (lane & 15)) * 256);
    uint32_t bRowG[5];
#pragma unroll
    for (int g = 0; g < 5; g++)
        bRowG[g] = (uint32_t)((im + 80 * h + 16 * g + ((lane >> 4) << 3) + (lane & 7)) * 256);

    const int er = lane >> 2;
    const int ec = (lane & 3) * 2;

    // ---- stage Q (hi/lo) ----
#pragma unroll
    for (int r = 0; r < 8; r++) {
        int idx = tid + NTHREADS * r;
        int row = idx >> 5, cv = idx & 31;
        float4 v = *reinterpret_cast<const float4*>(Qb + (size_t)(w0 + row) * CDIM + cv * 4);
        st_hilo4(smem, B_OQH, B_OQL, row, cv, v);
    }
    // ---- stage K panel: 272 rows (clamped), hi/lo ----
#pragma unroll
    for (int r = 0; r < 17; r++) {
        int idx = tid + NTHREADS * r;           // 8704 = 272*32 exactly
        int row = idx >> 5, cv = idx & 31;
        int u = u0 + row;
        if (u > 2046) u = 2046;
        float4 v = *reinterpret_cast<const float4*>(Kb + (size_t)u * CDIM + cv * 4);
        st_hilo4(smem, B_OPH, B_OPL, row, cv, v);
    }
    __syncthreads();

    // ---- band GEMM: acc[10 n-frags][4] ----
    float acc[10][4];
#pragma unroll
    for (int n = 0; n < 10; n++)
#pragma unroll
        for (int e = 0; e < 4; e++) acc[n][e] = 0.f;

#pragma unroll
    for (int st = 0; st < 8; st++) {
        uint32_t kc = 2u * (uint32_t)st;
        uint32_t aoff = ((kc + aC2) ^ rx) << 4;
        uint32_t boff = ((kc + bC2) ^ rx) << 4;
        uint32_t ah0,ah1,ah2,ah3, al0,al1,al2,al3;
        ldsm4(sb + B_OQH + aRowB + aoff, ah0,ah1,ah2,ah3);
        ldsm4(sb + B_OQL + aRowB + aoff, al0,al1,al2,al3);
#pragma unroll
        for (int g = 0; g < 5; g++) {
            uint32_t bh0,bh1,bh2,bh3, bl0,bl1,bl2,bl3;
            ldsm4(sb + B_OPH + bRowG[g] + boff, bh0,bh1,bh2,bh3);
            ldsm4(sb + B_OPL + bRowG[g] + boff, bl0,bl1,bl2,bl3);
            mma16816(acc[2*g    ], ah0,ah1,ah2,ah3, bh0,bh1);
            mma16816(acc[2*g + 1], ah0,ah1,ah2,ah3, bh2,bh3);
            mma16816(acc[2*g    ], ah0,ah1,ah2,ah3, bl0,bl1);
            mma16816(acc[2*g + 1], ah0,ah1,ah2,ah3, bl2,bl3);
            mma16816(acc[2*g    ], al0,al1,al2,al3, bh0,bh1);
            mma16816(acc[2*g + 1], al0,al1,al2,al3, bh2,bh3);
        }
    }
    __syncthreads();   // all panel reads done before Z overlay

    // ---- scatter (pure assignment): Z[i, j-r] = D[r, j] ----
#pragma unroll
    for (int nf = 0; nf < 10; nf++)
#pragma unroll
        for (int e = 0; e < 4; e++) {
            int r = er + ((e & 2) ? 8 : 0);
            int j = 80 * h + nf * 8 + ec + (e & 1);
            int tau = j - r;
            if ((unsigned)tau < 128u)
                zs[(im + r) * ZSTRIDE + tau] = acc[nf][e];
        }
    __syncthreads();

    // ---- writeout: Z += zs (coalesced float4 RMW) ----
#pragma unroll
    for (int r = 0; r < 8; r++) {
        int idx = tid + NTHREADS * r;
        int row = idx >> 5, tv = idx & 31;
        float4 a = *reinterpret_cast<const float4*>(zs + row * ZSTRIDE + tv * 4);
        float4 z = *reinterpret_cast<const float4*>(Zb + (size_t)row * TDIM + tv * 4);
        z.x += a.x; z.y += a.y; z.z += a.z; z.w += a.w;
        *reinterpret_cast<float4*>(Zb + (size_t)row * TDIM + tv * 4) = z;
    }
}

extern "C" void kernel_launch(void* const* d_in, const int* in_sizes, int n_in,
                              void* d_out, int out_size)
{
    const float* Q    = (const float*)d_in[0];   // (16, 1024, 128)
    const float* Km   = (const float*)d_in[1];   // (16, 2047, 128)
    const float* bias = (const float*)d_in[2];   // (1, 1, 128, 1024)
    float* Z          = (float*)d_out;           // (16, 1024, 1024)

    static int inited = 0;
    cudaFuncSetAttribute(pb_kernel,   cudaFuncAttributeMaxDynamicSharedMemorySize, SMEM1);
    cudaFuncSetAttribute(band_kernel, cudaFuncAttributeMaxDynamicSharedMemorySize, SMEM2);
    (void)inited;

    dim3 grid(TDIM / 128, TDIM / 128, 16);       // (8, 8, 16)
    pb_kernel<<<grid, NTHREADS, SMEM1>>>(Q, bias, Z);
    band_kernel<<<grid, NTHREADS, SMEM2>>>(Q, Km, Z);
}

// round 8
// speedup vs baseline: 2.3312x; 1.2914x over previous
#include <cuda_runtime.h>
#include <cuda_bf16.h>
#include <cstdint>

// Z[b,w,t] = sum_c Q[b,w,c] * ( K[b,w+t,c] + bias[c,t] ),  B=16, T=1024, C=128.
//
// ONE kernel per 128x128 tile (b, w0, t0), u0 = w0+t0:
//  1) band GEMM: per warp (mt = wid>>1, h = wid&1), rows [16mt,16mt+16):
//       D[r,j] = sum_c Q[w0+16mt+r, c] * K[u0+16mt+j, c], j in [80h, 80h+80)
//     scatter-assign D[r,j] -> zs[16mt+r, j-r]  (0 <= j-r < 128; disjoint)
//  2) bias GEMM: PB[i,s] = sum_c Q[w0+i,c] * bias[c, t0+s]
//     epilogue: Z[w0+i, t0+s] = zs[i,s] + PB[i,s]   (single direct STG)
// GEMMs: merged k-loop AhBh + AhBl + AlBh (bf16 hi/lo split, fp32 accum).

#define TDIM   1024
#define CDIM   128
#define KROWS  2047
#define NTHREADS 512

// ---- smem layout (bytes) ----
#define OQH 0
#define OQL 32768
#define OPH 65536                       // K panel hi (272 rows x 256B)
#define PANEL_BYTES (272 * 256)         // 69632
#define OPL (OPH + PANEL_BYTES)         // 135168  K panel lo
#define SMEM_BYTES (OPL + PANEL_BYTES)  // 204800
// overlays (valid after band GEMM):
#define OZS OPH                         // fp32 Z buffer, 128 x ZSTRIDE (67584 B <= 69632)
#define ZSTRIDE 132
#define OBH OPL                         // bias B hi (128 x 256B)
#define OBL (OPL + 32768)               // bias B lo

__device__ __forceinline__ void ldsm4(uint32_t addr, uint32_t& r0, uint32_t& r1,
                                      uint32_t& r2, uint32_t& r3) {
    asm volatile("ldmatrix.sync.aligned.m8n8.x4.shared.b16 {%0,%1,%2,%3}, [%4];"
                 : "=r"(r0), "=r"(r1), "=r"(r2), "=r"(r3) : "r"(addr));
}
__device__ __forceinline__ void mma16816(float* d, uint32_t a0, uint32_t a1,
                                         uint32_t a2, uint32_t a3,
                                         uint32_t b0, uint32_t b1) {
    asm volatile("mma.sync.aligned.m16n8k16.row.col.f32.bf16.bf16.f32 "
                 "{%0,%1,%2,%3}, {%4,%5,%6,%7}, {%8,%9}, {%0,%1,%2,%3};"
                 : "+f"(d[0]), "+f"(d[1]), "+f"(d[2]), "+f"(d[3])
                 : "r"(a0), "r"(a1), "r"(a2), "r"(a3), "r"(b0), "r"(b1));
}
__device__ __forceinline__ uint32_t smem_u32(const void* p) {
    uint32_t a;
    asm("{ .reg .u64 t; cvta.to.shared.u64 t, %1; cvt.u32.u64 %0, t; }" : "=r"(a) : "l"(p));
    return a;
}
__device__ __forceinline__ uint32_t pack_hi_lo(float x, float y, uint32_t& lo_out) {
    __nv_bfloat16 hx = __float2bfloat16(x);
    __nv_bfloat16 hy = __float2bfloat16(y);
    __nv_bfloat16 lx = __float2bfloat16(x - __bfloat162float(hx));
    __nv_bfloat16 ly = __float2bfloat16(y - __bfloat162float(hy));
    __nv_bfloat162 h = __nv_bfloat162(hx, hy);
    __nv_bfloat162 l = __nv_bfloat162(lx, ly);
    lo_out = *reinterpret_cast<uint32_t*>(&l);
    return *reinterpret_cast<uint32_t*>(&h);
}
// store float4 (4 c-values) of row `row` at c = cv*4 into hi/lo bf16 buffers
__device__ __forceinline__ void st_hilo4(char* sm, int bufH, int bufL,
                                         int row, int cv, float4 v) {
    uint32_t l01, l23;
    uint32_t h01 = pack_hi_lo(v.x, v.y, l01);
    uint32_t h23 = pack_hi_lo(v.z, v.w, l23);
    int c2 = cv >> 1;
    uint32_t off = (uint32_t)(row * 256 + (((c2) ^ (row & 7)) << 4) + (cv & 1) * 8);
    *reinterpret_cast<uint2*>(sm + bufH + off) = make_uint2(h01, h23);
    *reinterpret_cast<uint2*>(sm + bufL + off) = make_uint2(l01, l23);
}

__global__ __launch_bounds__(NTHREADS, 1)
void sw_fused_kernel(const float* __restrict__ Q,
                     const float* __restrict__ Km,
                     const float* __restrict__ bias,
                     float* __restrict__ Z)
{
    extern __shared__ char smem[];
    const uint32_t sb = smem_u32(smem);
    float* zs = reinterpret_cast<float*>(smem + OZS);

    const int tid  = threadIdx.x;
    const int wid  = tid >> 5;
    const int lane = tid & 31;

    const int b  = blockIdx.z;
    const int w0 = blockIdx.y * 128;
    const int t0 = blockIdx.x * 128;
    const int u0 = w0 + t0;

    const float* Qb = Q  + ((size_t)b * TDIM) * CDIM;
    const float* Kb = Km + ((size_t)b * KROWS) * CDIM;
    float* Zb = Z + ((size_t)b * TDIM + w0) * TDIM + t0;

    const uint32_t rx  = lane & 7;
    const uint32_t aC2 = lane >> 4;
    const uint32_t bC2 = (lane >> 3) & 1;
    const int er = lane >> 2;
    const int ec = (lane & 3) * 2;

    // ===================== stage Q (hi/lo) =====================
#pragma unroll
    for (int r = 0; r < 8; r++) {
        int idx = tid + NTHREADS * r;           // 4096 float4
        int row = idx >> 5, cv = idx & 31;
        float4 v = *reinterpret_cast<const float4*>(Qb + (size_t)(w0 + row) * CDIM + cv * 4);
        st_hilo4(smem, OQH, OQL, row, cv, v);
    }
    // ===================== stage K panel (272 rows, hi/lo) =====================
#pragma unroll
    for (int r = 0; r < 17; r++) {
        int idx = tid + NTHREADS * r;           // 8704 = 272*32 exactly
        int row = idx >> 5, cv = idx & 31;
        int u = u0 + row;
        if (u > 2046) u = 2046;                 // clamped rows only feed discarded taus
        float4 v = *reinterpret_cast<const float4*>(Kb + (size_t)u * CDIM + cv * 4);
        st_hilo4(smem, OPH, OPL, row, cv, v);
    }
    __syncthreads();

    // ===================== band GEMM =====================
    // warp: mt = wid>>1 (rows [16mt,16mt+16)), h = wid&1 (j in [80h,80h+80))
    {
        const int mt = wid >> 1;
        const int h  = wid & 1;
        const int im = mt * 16;
        const uint32_t aRowB = (uint32_t)((im + (lane & 15)) * 256);
        uint32_t bRowG[5];
#pragma unroll
        for (int g = 0; g < 5; g++)
            bRowG[g] = (uint32_t)((im + 80 * h + 16 * g + ((lane >> 4) << 3) + (lane & 7)) * 256);

        float acc[10][4];
#pragma unroll
        for (int n = 0; n < 10; n++)
#pragma unroll
            for (int e = 0; e < 4; e++) acc[n][e] = 0.f;

#pragma unroll
        for (int st = 0; st < 8; st++) {
            uint32_t kc = 2u * (uint32_t)st;
            uint32_t aoff = ((kc + aC2) ^ rx) << 4;
            uint32_t boff = ((kc + bC2) ^ rx) << 4;
            uint32_t ah0,ah1,ah2,ah3, al0,al1,al2,al3;
            ldsm4(sb + OQH + aRowB + aoff, ah0,ah1,ah2,ah3);
            ldsm4(sb + OQL + aRowB + aoff, al0,al1,al2,al3);
#pragma unroll
            for (int g = 0; g < 5; g++) {
                uint32_t bh0,bh1,bh2,bh3, bl0,bl1,bl2,bl3;
                ldsm4(sb + OPH + bRowG[g] + boff, bh0,bh1,bh2,bh3);
                ldsm4(sb + OPL + bRowG[g] + boff, bl0,bl1,bl2,bl3);
                mma16816(acc[2*g    ], ah0,ah1,ah2,ah3, bh0,bh1);
                mma16816(acc[2*g + 1], ah0,ah1,ah2,ah3, bh2,bh3);
                mma16816(acc[2*g    ], ah0,ah1,ah2,ah3, bl0,bl1);
                mma16816(acc[2*g + 1], ah0,ah1,ah2,ah3, bl2,bl3);
                mma16816(acc[2*g    ], al0,al1,al2,al3, bh0,bh1);
                mma16816(acc[2*g + 1], al0,al1,al2,al3, bh2,bh3);
            }
        }

        // ---- prefetch bias gather into regs (drains under sync + scatter) ----
        const int btau = tid >> 2;
        const int bcb  = (tid & 3) * 32;
        float f[32];
#pragma unroll
        for (int j = 0; j < 32; j++)
            f[j] = __ldg(bias + (size_t)(bcb + j) * TDIM + t0 + btau);

        __syncthreads();   // all panel reads done before overlays are written

        // ---- scatter (pure assignment): zs[im+r, j-r] = D[r, j] ----
#pragma unroll
        for (int nf = 0; nf < 10; nf++)
#pragma unroll
            for (int e = 0; e < 4; e++) {
                int r = er + ((e & 2) ? 8 : 0);
                int j = 80 * h + nf * 8 + ec + (e & 1);
                int tau = j - r;
                if ((unsigned)tau < 128u)
                    zs[(im + r) * ZSTRIDE + tau] = acc[nf][e];
            }

        // ---- convert bias regs -> B buffers (overlay on panel-lo) ----
#pragma unroll
        for (int j = 0; j < 16; j++) {
            uint32_t lo;
            uint32_t hi = pack_hi_lo(f[2 * j], f[2 * j + 1], lo);
            int c = bcb + 2 * j;
            int c2 = c >> 3;
            uint32_t off = (uint32_t)(btau * 256 + ((c2 ^ (btau & 7)) << 4) + ((c * 2) & 15));
            *reinterpret_cast<uint32_t*>(smem + OBH + off) = hi;
            *reinterpret_cast<uint32_t*>(smem + OBL + off) = lo;
        }
    }
    __syncthreads();

    // ===================== bias GEMM + fused epilogue =====================
    {
        const int wr = wid >> 2;            // 0..3
        const int wc = wid & 3;             // 0..3
        uint32_t aRow[2], bRow[2];
#pragma unroll
        for (int mt = 0; mt < 2; mt++)
            aRow[mt] = (uint32_t)((wr * 32 + mt * 16 + (lane & 15)) * 256);
#pragma unroll
        for (int p = 0; p < 2; p++)
            bRow[p] = (uint32_t)((wc * 32 + p * 16 + ((lane >> 4) << 3) + (lane & 7)) * 256);

        float acc[2][4][4];
#pragma unroll
        for (int m = 0; m < 2; m++)
#pragma unroll
            for (int n = 0; n < 4; n++)
#pragma unroll
                for (int e = 0; e < 4; e++) acc[m][n][e] = 0.f;

#pragma unroll
        for (int st = 0; st < 8; st++) {
            uint32_t kc = 2u * (uint32_t)st;
            uint32_t aoff = ((kc + aC2) ^ rx) << 4;
            uint32_t boff = ((kc + bC2) ^ rx) << 4;
            uint32_t ah0,ah1,ah2,ah3,ah4,ah5,ah6,ah7;
            uint32_t al0,al1,al2,al3,al4,al5,al6,al7;
            uint32_t bh0,bh1,bh2,bh3,bh4,bh5,bh6,bh7;
            uint32_t bl0,bl1,bl2,bl3,bl4,bl5,bl6,bl7;
            ldsm4(sb + OQH + aRow[0] + aoff, ah0,ah1,ah2,ah3);
            ldsm4(sb + OQH + aRow[1] + aoff, ah4,ah5,ah6,ah7);
            ldsm4(sb + OQL + aRow[0] + aoff, al0,al1,al2,al3);
            ldsm4(sb + OQL + aRow[1] + aoff, al4,al5,al6,al7);
            ldsm4(sb + OBH + bRow[0] + boff, bh0,bh1,bh2,bh3);
            ldsm4(sb + OBH + bRow[1] + boff, bh4,bh5,bh6,bh7);
            ldsm4(sb + OBL + bRow[0] + boff, bl0,bl1,bl2,bl3);
            ldsm4(sb + OBL + bRow[1] + boff, bl4,bl5,bl6,bl7);
            mma16816(acc[0][0], ah0,ah1,ah2,ah3, bh0,bh1);
            mma16816(acc[0][1], ah0,ah1,ah2,ah3, bh2,bh3);
            mma16816(acc[0][2], ah0,ah1,ah2,ah3, bh4,bh5);
            mma16816(acc[0][3], ah0,ah1,ah2,ah3, bh6,bh7);
            mma16816(acc[1][0], ah4,ah5,ah6,ah7, bh0,bh1);
            mma16816(acc[1][1], ah4,ah5,ah6,ah7, bh2,bh3);
            mma16816(acc[1][2], ah4,ah5,ah6,ah7, bh4,bh5);
            mma16816(acc[1][3], ah4,ah5,ah6,ah7, bh6,bh7);
            mma16816(acc[0][0], ah0,ah1,ah2,ah3, bl0,bl1);
            mma16816(acc[0][1], ah0,ah1,ah2,ah3, bl2,bl3);
            mma16816(acc[0][2], ah0,ah1,ah2,ah3, bl4,bl5);
            mma16816(acc[0][3], ah0,ah1,ah2,ah3, bl6,bl7);
            mma16816(acc[1][0], ah4,ah5,ah6,ah7, bl0,bl1);
            mma16816(acc[1][1], ah4,ah5,ah6,ah7, bl2,bl3);
            mma16816(acc[1][2], ah4,ah5,ah6,ah7, bl4,bl5);
            mma16816(acc[1][3], ah4,ah5,ah6,ah7, bl6,bl7);
            mma16816(acc[0][0], al0,al1,al2,al3, bh0,bh1);
            mma16816(acc[0][1], al0,al1,al2,al3, bh2,bh3);
            mma16816(acc[0][2], al0,al1,al2,al3, bh4,bh5);
            mma16816(acc[0][3], al0,al1,al2,al3, bh6,bh7);
            mma16816(acc[1][0], al4,al5,al6,al7, bh0,bh1);
            mma16816(acc[1][1], al4,al5,al6,al7, bh2,bh3);
            mma16816(acc[1][2], al4,al5,al6,al7, bh4,bh5);
            mma16816(acc[1][3], al4,al5,al6,al7, bh6,bh7);
        }

        // ---- epilogue: Z = zs + PB, direct STG ----
#pragma unroll
        for (int mt = 0; mt < 2; mt++)
#pragma unroll
            for (int nt = 0; nt < 4; nt++) {
                int i0  = wr * 32 + mt * 16 + er;
                int tau = wc * 32 + nt * 8 + ec;
                const float* z0 = zs + i0 * ZSTRIDE + tau;
                const float* z1 = zs + (i0 + 8) * ZSTRIDE + tau;
                *reinterpret_cast<float2*>(Zb + (size_t)i0 * TDIM + tau) =
                    make_float2(acc[mt][nt][0] + z0[0], acc[mt][nt][1] + z0[1]);
                *reinterpret_cast<float2*>(Zb + (size_t)(i0 + 8) * TDIM + tau) =
                    make_float2(acc[mt][nt][2] + z1[0], acc[mt][nt][3] + z1[1]);
            }
    }
}

extern "C" void kernel_launch(void* const* d_in, const int* in_sizes, int n_in,
                              void* d_out, int out_size)
{
    const float* Q    = (const float*)d_in[0];   // (16, 1024, 128)
    const float* Km   = (const float*)d_in[1];   // (16, 2047, 128)
    const float* bias = (const float*)d_in[2];   // (1, 1, 128, 1024)
    float* Z          = (float*)d_out;           // (16, 1024, 1024)

    cudaFuncSetAttribute(sw_fused_kernel, cudaFuncAttributeMaxDynamicSharedMemorySize, SMEM_BYTES);
    dim3 grid(TDIM / 128, TDIM / 128, 16);       // (8, 8, 16) = 1024 CTAs
    sw_fused_kernel<<<grid, NTHREADS, SMEM_BYTES>>>(Q, Km, bias, Z);
}